// round 4
// baseline (speedup 1.0000x reference)
#include <cuda_runtime.h>
#include <cuda_bf16.h>
#include <cstdint>

// ============================================================================
// DeformableCurrents: e_ss - 2 e_st + e_tt
//   == sum over combined set (src ∪ tar) of K(c_p,c_q) * (w_p . w_q),
//   w = +normal (src), -normal (tar).  f symmetric =>
//   S = 2 * sum_{tile_i < tile_j} + sum_diag.
//
// v4: packed fma.rn.f32x2 inner loop + 4 resident blocks/SM
//   (8 warps/SMSP = 16 independent rcp-chains in flight) to cover the
//   ~45-cycle chain latency. Grid 544 blocks -> fully resident, one wave.
// ============================================================================

#define THREADS   256
#define IPT       4                  // i-points per thread (2 packed chains)
#define ICHUNK    (THREADS * IPT)    // 1024
#define TJ        256                // j-subtile (== smem tile)
#define JSUB      (ICHUNK / TJ)      // 4 j-subtiles per tile-pair
#define MAX_PTS   20480

typedef unsigned long long u64;

__device__ float4 g_I[2 * MAX_PTS];
__device__ float4 g_J[2 * MAX_PTS];
__device__ double g_partials[1024];

// ---- packed f32x2 helpers ---------------------------------------------------
__device__ __forceinline__ u64 fma2(u64 a, u64 b, u64 c) {
    u64 d; asm("fma.rn.f32x2 %0, %1, %2, %3;" : "=l"(d) : "l"(a), "l"(b), "l"(c));
    return d;
}
__device__ __forceinline__ u64 add2(u64 a, u64 b) {
    u64 d; asm("add.rn.f32x2 %0, %1, %2;" : "=l"(d) : "l"(a), "l"(b));
    return d;
}
__device__ __forceinline__ u64 mul2(u64 a, u64 b) {
    u64 d; asm("mul.rn.f32x2 %0, %1, %2;" : "=l"(d) : "l"(a), "l"(b));
    return d;
}
__device__ __forceinline__ u64 pack2(float lo, float hi) {
    u64 d; asm("mov.b64 %0, {%1, %2};" : "=l"(d) : "f"(lo), "f"(hi));
    return d;
}
__device__ __forceinline__ void unpack2(u64 p, float& lo, float& hi) {
    asm("mov.b64 {%0, %1}, %2;" : "=f"(lo), "=f"(hi) : "l"(p));
}
__device__ __forceinline__ float rcpf(float x) {
    float r; asm("rcp.approx.ftz.f32 %0, %1;" : "=f"(r) : "f"(x));
    return r;
}

// ----------------------------------------------------------------------------
__global__ void prep_kernel(const float* __restrict__ verts,
                            const float* __restrict__ tnorm,
                            const float* __restrict__ tcent,
                            const int*   __restrict__ sidx,
                            int N, int M, int total_pad)
{
    int t = blockIdx.x * blockDim.x + threadIdx.x;
    if (t >= total_pad) return;

    float cx = 0.f, cy = 0.f, cz = 0.f;
    float wx = 0.f, wy = 0.f, wz = 0.f;

    if (t < N) {
        int i0 = sidx[3 * t + 0];
        int i1 = sidx[3 * t + 1];
        int i2 = sidx[3 * t + 2];
        float ax = verts[3 * i0], ay = verts[3 * i0 + 1], az = verts[3 * i0 + 2];
        float bx = verts[3 * i1], by = verts[3 * i1 + 1], bz = verts[3 * i1 + 2];
        float gx = verts[3 * i2], gy = verts[3 * i2 + 1], gz = verts[3 * i2 + 2];
        float e1x = ax - bx, e1y = ay - by, e1z = az - bz;
        float e2x = gx - bx, e2y = gy - by, e2z = gz - bz;
        wx = 0.5f * (e1y * e2z - e1z * e2y);
        wy = 0.5f * (e1z * e2x - e1x * e2z);
        wz = 0.5f * (e1x * e2y - e1y * e2x);
        cx = (ax + bx + gx) * (1.0f / 3.0f);
        cy = (ay + by + gy) * (1.0f / 3.0f);
        cz = (az + bz + gz) * (1.0f / 3.0f);
    } else if (t < N + M) {
        int j = t - N;
        cx = tcent[3 * j];  cy = tcent[3 * j + 1];  cz = tcent[3 * j + 2];
        wx = -tnorm[3 * j]; wy = -tnorm[3 * j + 1]; wz = -tnorm[3 * j + 2];
    }
    // padding rows keep w = 0 -> contribute nothing (denom >= 1, rcp fine)

    float a2 = cx * cx + cy * cy + cz * cz;
    g_I[2 * t]     = make_float4(cx, cy, cz, a2);
    g_I[2 * t + 1] = make_float4(wx, wy, wz, 0.f);
    g_J[2 * t]     = make_float4(-2.f * cx, -2.f * cy, -2.f * cz, 1.f + a2);
    g_J[2 * t + 1] = make_float4(wx, wy, wz, 0.f);
}

// ----------------------------------------------------------------------------
__global__ __launch_bounds__(THREADS, 4)
void pair_kernel(int T /* tiles of ICHUNK */)
{
    // splatted j-subtile: 8 u64 per j (7 used + 1 pad) = 16 KB
    __shared__ __align__(16) u64 sj[TJ * 8];
    __shared__ double rbuf[THREADS];

    const int tid = threadIdx.x;

    // block -> (triangular tile-pair, j-subtile)
    int unit = blockIdx.x / JSUB;
    const int sub = blockIdx.x % JSUB;
    int ti = 0, row = T;
    while (unit >= row) { unit -= row; ti++; row--; }
    const int tj = ti + unit;
    const float scale = (ti == tj) ? 1.0f : 2.0f;

    const int ibase = ti * ICHUNK;
    const int jt    = tj * ICHUNK + sub * TJ;

    // Fill splatted j-subtile once.
    {
        int j = jt + tid;
        float4 jc = g_J[2 * j];
        float4 jw = g_J[2 * j + 1];
        float* s = (float*)&sj[tid * 8];
        s[0]  = jc.x; s[1]  = jc.x;   // -2cx
        s[2]  = jc.y; s[3]  = jc.y;   // -2cy
        s[4]  = jc.z; s[5]  = jc.z;   // -2cz
        s[6]  = jc.w; s[7]  = jc.w;   // 1+|c|^2
        s[8]  = jw.x; s[9]  = jw.x;
        s[10] = jw.y; s[11] = jw.y;
        s[12] = jw.z; s[13] = jw.z;
    }

    // Load my IPT=4 i-points, pack pairs (0,1) and (2,3) component-wise.
    u64 pcx[2], pcy[2], pcz[2], pa2[2], pwx[2], pwy[2], pwz[2], acc[2];
#pragma unroll
    for (int c = 0; c < 2; c++) {
        int iA = ibase + (2 * c + 0) * THREADS + tid;
        int iB = ibase + (2 * c + 1) * THREADS + tid;
        float4 cA = g_I[2 * iA], wA = g_I[2 * iA + 1];
        float4 cB = g_I[2 * iB], wB = g_I[2 * iB + 1];
        pcx[c] = pack2(cA.x, cB.x);
        pcy[c] = pack2(cA.y, cB.y);
        pcz[c] = pack2(cA.z, cB.z);
        pa2[c] = pack2(cA.w, cB.w);
        pwx[c] = pack2(wA.x, wB.x);
        pwy[c] = pack2(wA.y, wB.y);
        pwz[c] = pack2(wA.z, wB.z);
        acc[c] = 0ull;
    }

    __syncthreads();

#pragma unroll 8
    for (int jj = 0; jj < TJ; jj++) {
        const ulonglong2* jp = (const ulonglong2*)&sj[jj * 8];
        ulonglong2 v0 = jp[0];   // {-2cx, -2cy}
        ulonglong2 v1 = jp[1];   // {-2cz, b}
        ulonglong2 v2 = jp[2];   // {wx, wy}
        ulonglong2 v3 = jp[3];   // {wz, pad}
#pragma unroll
        for (int c = 0; c < 2; c++) {
            u64 d = add2(pa2[c], v1.y);          // a_i + b_j
            d = fma2(v0.x, pcx[c], d);
            d = fma2(v0.y, pcy[c], d);
            d = fma2(v1.x, pcz[c], d);           // = 1 + |ci-cj|^2
            float d0, d1; unpack2(d, d0, d1);
            u64 r = pack2(rcpf(d0), rcpf(d1));
            u64 t = mul2(pwx[c], v2.x);
            t = fma2(pwy[c], v2.y, t);
            t = fma2(pwz[c], v3.x, t);
            acc[c] = fma2(t, r, acc[c]);
        }
    }

    // Deterministic block reduction in double, with triangular scale.
    float a0, a1, a2f, a3;
    unpack2(acc[0], a0, a1);
    unpack2(acc[1], a2f, a3);
    double s = (double)scale * (((double)a0 + (double)a1) +
                                ((double)a2f + (double)a3));
    rbuf[tid] = s;
    __syncthreads();
#pragma unroll
    for (int off = THREADS / 2; off > 0; off >>= 1) {
        if (tid < off) rbuf[tid] += rbuf[tid + off];
        __syncthreads();
    }
    if (tid == 0)
        g_partials[blockIdx.x] = rbuf[0];
}

// ----------------------------------------------------------------------------
__global__ void reduce_kernel(float* __restrict__ out, int nP)
{
    __shared__ double r[1024];
    int tid = threadIdx.x;
    r[tid] = (tid < nP) ? g_partials[tid] : 0.0;
    __syncthreads();
#pragma unroll
    for (int off = 512; off > 0; off >>= 1) {
        if (tid < off) r[tid] += r[tid + off];
        __syncthreads();
    }
    if (tid == 0) out[0] = (float)r[0];
}

// ----------------------------------------------------------------------------
extern "C" void kernel_launch(void* const* d_in, const int* in_sizes, int n_in,
                              void* d_out, int out_size)
{
    const float* verts = (const float*)d_in[0];   // src_vertices  (V,3)
    const float* tnorm = (const float*)d_in[1];   // tar_normals   (M,3)
    const float* tcent = (const float*)d_in[2];   // tar_centers   (M,3)
    const int*   sidx  = (const int*)  d_in[3];   // src_indices   (N,3)

    const int N = in_sizes[3] / 3;
    const int M = in_sizes[1] / 3;
    const int total = N + M;
    const int total_pad = ((total + ICHUNK - 1) / ICHUNK) * ICHUNK;
    const int T = total_pad / ICHUNK;             // 16 for 16384 points

    prep_kernel<<<(total_pad + THREADS - 1) / THREADS, THREADS>>>(
        verts, tnorm, tcent, sidx, N, M, total_pad);

    const int nBlocks = (T * (T + 1) / 2) * JSUB;   // 544
    pair_kernel<<<nBlocks, THREADS>>>(T);

    reduce_kernel<<<1, 1024>>>((float*)d_out, nBlocks);
}

// round 5
// speedup vs baseline: 1.0068x; 1.0068x over previous
#include <cuda_runtime.h>
#include <cuda_bf16.h>
#include <cstdint>

// ============================================================================
// DeformableCurrents: e_ss - 2 e_st + e_tt
//   == sum over combined set (src ∪ tar) of K(c_p,c_q)*(w_p.w_q),
//   w = +normal (src), -normal (tar); f symmetric => triangular tiles.
//
// v5: SINGLE fused kernel.
//   - per-block prep: i-points straight into registers, j-points into
//     splatted smem (no global staging, no prep kernel)
//   - packed fma.rn.f32x2 inner loop (at its RF-bank floor, unchanged)
//   - deterministic last-block reduction (fixed-order tree), ticket counter
//     self-resets for graph replay
// ============================================================================

#define THREADS   256
#define IPT       4                  // i-points per thread (2 packed chains)
#define ICHUNK    (THREADS * IPT)    // 1024
#define TJ        256                // j-subtile (== smem tile)
#define JSUB      (ICHUNK / TJ)      // 4

typedef unsigned long long u64;

__device__ double g_partials[1024];
__device__ unsigned int g_done = 0;

// ---- packed f32x2 helpers ---------------------------------------------------
__device__ __forceinline__ u64 fma2(u64 a, u64 b, u64 c) {
    u64 d; asm("fma.rn.f32x2 %0, %1, %2, %3;" : "=l"(d) : "l"(a), "l"(b), "l"(c));
    return d;
}
__device__ __forceinline__ u64 add2(u64 a, u64 b) {
    u64 d; asm("add.rn.f32x2 %0, %1, %2;" : "=l"(d) : "l"(a), "l"(b));
    return d;
}
__device__ __forceinline__ u64 mul2(u64 a, u64 b) {
    u64 d; asm("mul.rn.f32x2 %0, %1, %2;" : "=l"(d) : "l"(a), "l"(b));
    return d;
}
__device__ __forceinline__ u64 pack2(float lo, float hi) {
    u64 d; asm("mov.b64 %0, {%1, %2};" : "=l"(d) : "f"(lo), "f"(hi));
    return d;
}
__device__ __forceinline__ void unpack2(u64 p, float& lo, float& hi) {
    asm("mov.b64 {%0, %1}, %2;" : "=f"(lo), "=f"(hi) : "l"(p));
}
__device__ __forceinline__ float rcpf(float x) {
    float r; asm("rcp.approx.ftz.f32 %0, %1;" : "=f"(r) : "f"(x));
    return r;
}

// ---- per-point prep (center c, squared-norm a2, weight w) --------------------
__device__ __forceinline__ void make_point(
    int t, int N, int M,
    const float* __restrict__ verts, const float* __restrict__ tnorm,
    const float* __restrict__ tcent, const int* __restrict__ sidx,
    float& cx, float& cy, float& cz, float& a2,
    float& wx, float& wy, float& wz)
{
    cx = 0.f; cy = 0.f; cz = 0.f;
    wx = 0.f; wy = 0.f; wz = 0.f;
    if (t < N) {
        int i0 = sidx[3 * t + 0];
        int i1 = sidx[3 * t + 1];
        int i2 = sidx[3 * t + 2];
        float ax = verts[3 * i0], ay = verts[3 * i0 + 1], az = verts[3 * i0 + 2];
        float bx = verts[3 * i1], by = verts[3 * i1 + 1], bz = verts[3 * i1 + 2];
        float gx = verts[3 * i2], gy = verts[3 * i2 + 1], gz = verts[3 * i2 + 2];
        float e1x = ax - bx, e1y = ay - by, e1z = az - bz;
        float e2x = gx - bx, e2y = gy - by, e2z = gz - bz;
        wx = 0.5f * (e1y * e2z - e1z * e2y);
        wy = 0.5f * (e1z * e2x - e1x * e2z);
        wz = 0.5f * (e1x * e2y - e1y * e2x);
        cx = (ax + bx + gx) * (1.0f / 3.0f);
        cy = (ay + by + gy) * (1.0f / 3.0f);
        cz = (az + bz + gz) * (1.0f / 3.0f);
    } else if (t < N + M) {
        int j = t - N;
        cx = tcent[3 * j];  cy = tcent[3 * j + 1];  cz = tcent[3 * j + 2];
        wx = -tnorm[3 * j]; wy = -tnorm[3 * j + 1]; wz = -tnorm[3 * j + 2];
    }
    // padding: w = 0 -> zero contribution (denom >= 1, rcp safe)
    a2 = cx * cx + cy * cy + cz * cz;
}

// ----------------------------------------------------------------------------
__global__ __launch_bounds__(THREADS, 4)
void fused_kernel(const float* __restrict__ verts,
                  const float* __restrict__ tnorm,
                  const float* __restrict__ tcent,
                  const int*   __restrict__ sidx,
                  int N, int M, int T, int nBlocks,
                  float* __restrict__ out)
{
    // splatted j-subtile: 8 u64 per j (7 used + 1 pad) = 16 KB
    __shared__ __align__(16) u64 sj[TJ * 8];
    __shared__ double rbuf[THREADS];
    __shared__ int s_last;

    const int tid = threadIdx.x;

    // block -> (triangular tile-pair, j-subtile)
    int unit = blockIdx.x / JSUB;
    const int sub = blockIdx.x % JSUB;
    int ti = 0, row = T;
    while (unit >= row) { unit -= row; ti++; row--; }
    const int tj = ti + unit;
    const float scale = (ti == tj) ? 1.0f : 2.0f;

    const int ibase = ti * ICHUNK;
    const int jt    = tj * ICHUNK + sub * TJ;

    // ---- j prep + splat fill (1 j per thread) ----
    {
        int j = jt + tid;
        float cx, cy, cz, a2, wx, wy, wz;
        make_point(j, N, M, verts, tnorm, tcent, sidx, cx, cy, cz, a2, wx, wy, wz);
        u64* s = &sj[tid * 8];
        s[0] = pack2(-2.f * cx, -2.f * cx);
        s[1] = pack2(-2.f * cy, -2.f * cy);
        s[2] = pack2(-2.f * cz, -2.f * cz);
        s[3] = pack2(1.f + a2, 1.f + a2);
        s[4] = pack2(wx, wx);
        s[5] = pack2(wy, wy);
        s[6] = pack2(wz, wz);
    }

    // ---- i prep: IPT=4 points straight into packed registers ----
    u64 pcx[2], pcy[2], pcz[2], pa2[2], pwx[2], pwy[2], pwz[2], acc[2];
#pragma unroll
    for (int c = 0; c < 2; c++) {
        float cxA, cyA, czA, a2A, wxA, wyA, wzA;
        float cxB, cyB, czB, a2B, wxB, wyB, wzB;
        int iA = ibase + (2 * c + 0) * THREADS + tid;
        int iB = ibase + (2 * c + 1) * THREADS + tid;
        make_point(iA, N, M, verts, tnorm, tcent, sidx, cxA, cyA, czA, a2A, wxA, wyA, wzA);
        make_point(iB, N, M, verts, tnorm, tcent, sidx, cxB, cyB, czB, a2B, wxB, wyB, wzB);
        pcx[c] = pack2(cxA, cxB);
        pcy[c] = pack2(cyA, cyB);
        pcz[c] = pack2(czA, czB);
        pa2[c] = pack2(a2A, a2B);
        pwx[c] = pack2(wxA, wxB);
        pwy[c] = pack2(wyA, wyB);
        pwz[c] = pack2(wzA, wzB);
        acc[c] = 0ull;
    }

    __syncthreads();

    // ---- main pair loop (unchanged: at RF-bank floor) ----
#pragma unroll 8
    for (int jj = 0; jj < TJ; jj++) {
        const ulonglong2* jp = (const ulonglong2*)&sj[jj * 8];
        ulonglong2 v0 = jp[0];   // {-2cx, -2cy}
        ulonglong2 v1 = jp[1];   // {-2cz, b}
        ulonglong2 v2 = jp[2];   // {wx, wy}
        ulonglong2 v3 = jp[3];   // {wz, pad}
#pragma unroll
        for (int c = 0; c < 2; c++) {
            u64 d = add2(pa2[c], v1.y);          // a_i + b_j
            d = fma2(v0.x, pcx[c], d);
            d = fma2(v0.y, pcy[c], d);
            d = fma2(v1.x, pcz[c], d);           // = 1 + |ci-cj|^2
            float d0, d1; unpack2(d, d0, d1);
            u64 r = pack2(rcpf(d0), rcpf(d1));
            u64 t = mul2(pwx[c], v2.x);
            t = fma2(pwy[c], v2.y, t);
            t = fma2(pwz[c], v3.x, t);
            acc[c] = fma2(t, r, acc[c]);
        }
    }

    // ---- deterministic block reduction (double) ----
    float a0, a1, a2f, a3;
    unpack2(acc[0], a0, a1);
    unpack2(acc[1], a2f, a3);
    double s = (double)scale * (((double)a0 + (double)a1) +
                                ((double)a2f + (double)a3));
    rbuf[tid] = s;
    __syncthreads();
#pragma unroll
    for (int off = THREADS / 2; off > 0; off >>= 1) {
        if (tid < off) rbuf[tid] += rbuf[tid + off];
        __syncthreads();
    }
    if (tid == 0) {
        g_partials[blockIdx.x] = rbuf[0];
        __threadfence();
        unsigned int ticket = atomicAdd(&g_done, 1u);
        s_last = (ticket == (unsigned int)(nBlocks - 1)) ? 1 : 0;
    }
    __syncthreads();

    // ---- last block: fixed-order deterministic final reduction ----
    if (s_last) {
        double fs = 0.0;
        for (int k = tid; k < nBlocks; k += THREADS)   // fixed assignment+order
            fs += g_partials[k];
        rbuf[tid] = fs;
        __syncthreads();
#pragma unroll
        for (int off = THREADS / 2; off > 0; off >>= 1) {
            if (tid < off) rbuf[tid] += rbuf[tid + off];
            __syncthreads();
        }
        if (tid == 0) {
            out[0] = (float)rbuf[0];
            g_done = 0;   // self-restore for next graph replay
        }
    }
}

// ----------------------------------------------------------------------------
extern "C" void kernel_launch(void* const* d_in, const int* in_sizes, int n_in,
                              void* d_out, int out_size)
{
    const float* verts = (const float*)d_in[0];   // src_vertices  (V,3)
    const float* tnorm = (const float*)d_in[1];   // tar_normals   (M,3)
    const float* tcent = (const float*)d_in[2];   // tar_centers   (M,3)
    const int*   sidx  = (const int*)  d_in[3];   // src_indices   (N,3)

    const int N = in_sizes[3] / 3;
    const int M = in_sizes[1] / 3;
    const int total = N + M;
    const int total_pad = ((total + ICHUNK - 1) / ICHUNK) * ICHUNK;
    const int T = total_pad / ICHUNK;             // 16 for 16384 points

    const int nBlocks = (T * (T + 1) / 2) * JSUB;   // 544
    fused_kernel<<<nBlocks, THREADS>>>(verts, tnorm, tcent, sidx,
                                       N, M, T, nBlocks, (float*)d_out);
}

// round 6
// speedup vs baseline: 1.0385x; 1.0315x over previous
#include <cuda_runtime.h>
#include <cuda_bf16.h>
#include <cstdint>

// ============================================================================
// DeformableCurrents: e_ss - 2 e_st + e_tt
//   == sum over combined set (src ∪ tar) of K(c_p,c_q)*(w_p.w_q),
//   w = +normal (src), -normal (tar); f symmetric => triangular tiles.
//
// v6: IPT=8 (4 packed f32x2 chains/thread), 2 blocks/SM @128 regs.
//   Per warp-jj: 32 FFMA2 (64cyc fma) + 8 MUFU (64cyc) co-saturate both
//   pipes; issue overhead (LDS/loop) amortized 2x vs v5. 288 blocks = one
//   fully-resident wave. Single fused kernel w/ deterministic last-block sum.
// ============================================================================

#define THREADS   256
#define NCH       4                  // packed chains per thread
#define IPT       (2 * NCH)          // 8 i-points per thread
#define ICHUNK    (THREADS * IPT)    // 2048
#define TJ        256                // j-subtile (== smem tile)
#define JSUB      (ICHUNK / TJ)      // 8

typedef unsigned long long u64;

__device__ double g_partials[1024];
__device__ unsigned int g_done = 0;

// ---- packed f32x2 helpers ---------------------------------------------------
__device__ __forceinline__ u64 fma2(u64 a, u64 b, u64 c) {
    u64 d; asm("fma.rn.f32x2 %0, %1, %2, %3;" : "=l"(d) : "l"(a), "l"(b), "l"(c));
    return d;
}
__device__ __forceinline__ u64 add2(u64 a, u64 b) {
    u64 d; asm("add.rn.f32x2 %0, %1, %2;" : "=l"(d) : "l"(a), "l"(b));
    return d;
}
__device__ __forceinline__ u64 mul2(u64 a, u64 b) {
    u64 d; asm("mul.rn.f32x2 %0, %1, %2;" : "=l"(d) : "l"(a), "l"(b));
    return d;
}
__device__ __forceinline__ u64 pack2(float lo, float hi) {
    u64 d; asm("mov.b64 %0, {%1, %2};" : "=l"(d) : "f"(lo), "f"(hi));
    return d;
}
__device__ __forceinline__ void unpack2(u64 p, float& lo, float& hi) {
    asm("mov.b64 {%0, %1}, %2;" : "=f"(lo), "=f"(hi) : "l"(p));
}
__device__ __forceinline__ float rcpf(float x) {
    float r; asm("rcp.approx.ftz.f32 %0, %1;" : "=f"(r) : "f"(x));
    return r;
}

// ---- per-point prep (center c, squared-norm a2, weight w) --------------------
__device__ __forceinline__ void make_point(
    int t, int N, int M,
    const float* __restrict__ verts, const float* __restrict__ tnorm,
    const float* __restrict__ tcent, const int* __restrict__ sidx,
    float& cx, float& cy, float& cz, float& a2,
    float& wx, float& wy, float& wz)
{
    cx = 0.f; cy = 0.f; cz = 0.f;
    wx = 0.f; wy = 0.f; wz = 0.f;
    if (t < N) {
        int i0 = sidx[3 * t + 0];
        int i1 = sidx[3 * t + 1];
        int i2 = sidx[3 * t + 2];
        float ax = verts[3 * i0], ay = verts[3 * i0 + 1], az = verts[3 * i0 + 2];
        float bx = verts[3 * i1], by = verts[3 * i1 + 1], bz = verts[3 * i1 + 2];
        float gx = verts[3 * i2], gy = verts[3 * i2 + 1], gz = verts[3 * i2 + 2];
        float e1x = ax - bx, e1y = ay - by, e1z = az - bz;
        float e2x = gx - bx, e2y = gy - by, e2z = gz - bz;
        wx = 0.5f * (e1y * e2z - e1z * e2y);
        wy = 0.5f * (e1z * e2x - e1x * e2z);
        wz = 0.5f * (e1x * e2y - e1y * e2x);
        cx = (ax + bx + gx) * (1.0f / 3.0f);
        cy = (ay + by + gy) * (1.0f / 3.0f);
        cz = (az + bz + gz) * (1.0f / 3.0f);
    } else if (t < N + M) {
        int j = t - N;
        cx = tcent[3 * j];  cy = tcent[3 * j + 1];  cz = tcent[3 * j + 2];
        wx = -tnorm[3 * j]; wy = -tnorm[3 * j + 1]; wz = -tnorm[3 * j + 2];
    }
    // padding: w = 0 -> zero contribution (denom >= 1, rcp safe)
    a2 = cx * cx + cy * cy + cz * cz;
}

// ----------------------------------------------------------------------------
__global__ __launch_bounds__(THREADS, 2)
void fused_kernel(const float* __restrict__ verts,
                  const float* __restrict__ tnorm,
                  const float* __restrict__ tcent,
                  const int*   __restrict__ sidx,
                  int N, int M, int T, int nBlocks,
                  float* __restrict__ out)
{
    // splatted j-subtile: 8 u64 per j (7 used + 1 pad) = 16 KB
    __shared__ __align__(16) u64 sj[TJ * 8];
    __shared__ double rbuf[THREADS];
    __shared__ int s_last;

    const int tid = threadIdx.x;

    // block -> (triangular tile-pair, j-subtile)
    int unit = blockIdx.x / JSUB;
    const int sub = blockIdx.x % JSUB;
    int ti = 0, row = T;
    while (unit >= row) { unit -= row; ti++; row--; }
    const int tj = ti + unit;
    const float scale = (ti == tj) ? 1.0f : 2.0f;

    const int ibase = ti * ICHUNK;
    const int jt    = tj * ICHUNK + sub * TJ;

    // ---- j prep + splat fill (1 j per thread) ----
    {
        int j = jt + tid;
        float cx, cy, cz, a2, wx, wy, wz;
        make_point(j, N, M, verts, tnorm, tcent, sidx, cx, cy, cz, a2, wx, wy, wz);
        u64* s = &sj[tid * 8];
        s[0] = pack2(-2.f * cx, -2.f * cx);
        s[1] = pack2(-2.f * cy, -2.f * cy);
        s[2] = pack2(-2.f * cz, -2.f * cz);
        s[3] = pack2(1.f + a2, 1.f + a2);
        s[4] = pack2(wx, wx);
        s[5] = pack2(wy, wy);
        s[6] = pack2(wz, wz);
    }

    // ---- i prep: IPT=8 points straight into packed registers ----
    u64 pcx[NCH], pcy[NCH], pcz[NCH], pa2[NCH];
    u64 pwx[NCH], pwy[NCH], pwz[NCH], acc[NCH];
#pragma unroll
    for (int c = 0; c < NCH; c++) {
        float cxA, cyA, czA, a2A, wxA, wyA, wzA;
        float cxB, cyB, czB, a2B, wxB, wyB, wzB;
        int iA = ibase + (2 * c + 0) * THREADS + tid;
        int iB = ibase + (2 * c + 1) * THREADS + tid;
        make_point(iA, N, M, verts, tnorm, tcent, sidx, cxA, cyA, czA, a2A, wxA, wyA, wzA);
        make_point(iB, N, M, verts, tnorm, tcent, sidx, cxB, cyB, czB, a2B, wxB, wyB, wzB);
        pcx[c] = pack2(cxA, cxB);
        pcy[c] = pack2(cyA, cyB);
        pcz[c] = pack2(czA, czB);
        pa2[c] = pack2(a2A, a2B);
        pwx[c] = pack2(wxA, wxB);
        pwy[c] = pack2(wyA, wyB);
        pwz[c] = pack2(wzA, wzB);
        acc[c] = 0ull;
    }

    __syncthreads();

    // ---- main pair loop ----
#pragma unroll 4
    for (int jj = 0; jj < TJ; jj++) {
        const ulonglong2* jp = (const ulonglong2*)&sj[jj * 8];
        ulonglong2 v0 = jp[0];   // {-2cx, -2cy}
        ulonglong2 v1 = jp[1];   // {-2cz, b}
        ulonglong2 v2 = jp[2];   // {wx, wy}
        ulonglong2 v3 = jp[3];   // {wz, pad}
#pragma unroll
        for (int c = 0; c < NCH; c++) {
            u64 d = add2(pa2[c], v1.y);          // a_i + b_j
            d = fma2(v0.x, pcx[c], d);
            d = fma2(v0.y, pcy[c], d);
            d = fma2(v1.x, pcz[c], d);           // = 1 + |ci-cj|^2
            float d0, d1; unpack2(d, d0, d1);
            u64 r = pack2(rcpf(d0), rcpf(d1));
            u64 t = mul2(pwx[c], v2.x);
            t = fma2(pwy[c], v2.y, t);
            t = fma2(pwz[c], v3.x, t);
            acc[c] = fma2(t, r, acc[c]);
        }
    }

    // ---- deterministic block reduction (double) ----
    double s = 0.0;
#pragma unroll
    for (int c = 0; c < NCH; c++) {
        float a0, a1;
        unpack2(acc[c], a0, a1);
        s += (double)a0 + (double)a1;
    }
    s *= (double)scale;
    rbuf[tid] = s;
    __syncthreads();
#pragma unroll
    for (int off = THREADS / 2; off > 0; off >>= 1) {
        if (tid < off) rbuf[tid] += rbuf[tid + off];
        __syncthreads();
    }
    if (tid == 0) {
        g_partials[blockIdx.x] = rbuf[0];
        __threadfence();
        unsigned int ticket = atomicAdd(&g_done, 1u);
        s_last = (ticket == (unsigned int)(nBlocks - 1)) ? 1 : 0;
    }
    __syncthreads();

    // ---- last block: fixed-order deterministic final reduction ----
    if (s_last) {
        double fs = 0.0;
        for (int k = tid; k < nBlocks; k += THREADS)   // fixed assignment+order
            fs += g_partials[k];
        rbuf[tid] = fs;
        __syncthreads();
#pragma unroll
        for (int off = THREADS / 2; off > 0; off >>= 1) {
            if (tid < off) rbuf[tid] += rbuf[tid + off];
            __syncthreads();
        }
        if (tid == 0) {
            out[0] = (float)rbuf[0];
            g_done = 0;   // self-restore for next graph replay
        }
    }
}

// ----------------------------------------------------------------------------
extern "C" void kernel_launch(void* const* d_in, const int* in_sizes, int n_in,
                              void* d_out, int out_size)
{
    const float* verts = (const float*)d_in[0];   // src_vertices  (V,3)
    const float* tnorm = (const float*)d_in[1];   // tar_normals   (M,3)
    const float* tcent = (const float*)d_in[2];   // tar_centers   (M,3)
    const int*   sidx  = (const int*)  d_in[3];   // src_indices   (N,3)

    const int N = in_sizes[3] / 3;
    const int M = in_sizes[1] / 3;
    const int total = N + M;
    const int total_pad = ((total + ICHUNK - 1) / ICHUNK) * ICHUNK;
    const int T = total_pad / ICHUNK;             // 8 for 16384 points

    const int nBlocks = (T * (T + 1) / 2) * JSUB;   // 36 * 8 = 288
    fused_kernel<<<nBlocks, THREADS>>>(verts, tnorm, tcent, sidx,
                                       N, M, T, nBlocks, (float*)d_out);
}

// round 7
// speedup vs baseline: 1.0795x; 1.0395x over previous
#include <cuda_runtime.h>
#include <cuda_bf16.h>
#include <cstdint>

// ============================================================================
// DeformableCurrents: e_ss - 2 e_st + e_tt
//   == sum over combined set (src ∪ tar) of K(c_p,c_q)*(w_p.w_q),
//   w = +normal (src), -normal (tar); f symmetric => triangular tiles.
//
// v7: latency-exposure fixes on the v6 loop (math identical):
//   - register double-buffered j-tile (LDS prefetch one jj ahead)
//   - stage-batched chains per jj: 4 denoms -> 8 rcps (MUFU pipelined) ->
//     4 dots+accs, to expose cross-chain ILP explicitly
//   - unroll 8
// ============================================================================

#define THREADS   256
#define NCH       4                  // packed chains per thread
#define IPT       (2 * NCH)          // 8 i-points per thread
#define ICHUNK    (THREADS * IPT)    // 2048
#define TJ        256                // j-subtile (== smem tile)
#define JSUB      (ICHUNK / TJ)      // 8

typedef unsigned long long u64;

__device__ double g_partials[1024];
__device__ unsigned int g_done = 0;

// ---- packed f32x2 helpers ---------------------------------------------------
__device__ __forceinline__ u64 fma2(u64 a, u64 b, u64 c) {
    u64 d; asm("fma.rn.f32x2 %0, %1, %2, %3;" : "=l"(d) : "l"(a), "l"(b), "l"(c));
    return d;
}
__device__ __forceinline__ u64 add2(u64 a, u64 b) {
    u64 d; asm("add.rn.f32x2 %0, %1, %2;" : "=l"(d) : "l"(a), "l"(b));
    return d;
}
__device__ __forceinline__ u64 mul2(u64 a, u64 b) {
    u64 d; asm("mul.rn.f32x2 %0, %1, %2;" : "=l"(d) : "l"(a), "l"(b));
    return d;
}
__device__ __forceinline__ u64 pack2(float lo, float hi) {
    u64 d; asm("mov.b64 %0, {%1, %2};" : "=l"(d) : "f"(lo), "f"(hi));
    return d;
}
__device__ __forceinline__ void unpack2(u64 p, float& lo, float& hi) {
    asm("mov.b64 {%0, %1}, %2;" : "=f"(lo), "=f"(hi) : "l"(p));
}
__device__ __forceinline__ float rcpf(float x) {
    float r; asm("rcp.approx.ftz.f32 %0, %1;" : "=f"(r) : "f"(x));
    return r;
}

// ---- per-point prep (center c, squared-norm a2, weight w) --------------------
__device__ __forceinline__ void make_point(
    int t, int N, int M,
    const float* __restrict__ verts, const float* __restrict__ tnorm,
    const float* __restrict__ tcent, const int* __restrict__ sidx,
    float& cx, float& cy, float& cz, float& a2,
    float& wx, float& wy, float& wz)
{
    cx = 0.f; cy = 0.f; cz = 0.f;
    wx = 0.f; wy = 0.f; wz = 0.f;
    if (t < N) {
        int i0 = sidx[3 * t + 0];
        int i1 = sidx[3 * t + 1];
        int i2 = sidx[3 * t + 2];
        float ax = verts[3 * i0], ay = verts[3 * i0 + 1], az = verts[3 * i0 + 2];
        float bx = verts[3 * i1], by = verts[3 * i1 + 1], bz = verts[3 * i1 + 2];
        float gx = verts[3 * i2], gy = verts[3 * i2 + 1], gz = verts[3 * i2 + 2];
        float e1x = ax - bx, e1y = ay - by, e1z = az - bz;
        float e2x = gx - bx, e2y = gy - by, e2z = gz - bz;
        wx = 0.5f * (e1y * e2z - e1z * e2y);
        wy = 0.5f * (e1z * e2x - e1x * e2z);
        wz = 0.5f * (e1x * e2y - e1y * e2x);
        cx = (ax + bx + gx) * (1.0f / 3.0f);
        cy = (ay + by + gy) * (1.0f / 3.0f);
        cz = (az + bz + gz) * (1.0f / 3.0f);
    } else if (t < N + M) {
        int j = t - N;
        cx = tcent[3 * j];  cy = tcent[3 * j + 1];  cz = tcent[3 * j + 2];
        wx = -tnorm[3 * j]; wy = -tnorm[3 * j + 1]; wz = -tnorm[3 * j + 2];
    }
    // padding: w = 0 -> zero contribution (denom >= 1, rcp safe)
    a2 = cx * cx + cy * cy + cz * cz;
}

// ----------------------------------------------------------------------------
__global__ __launch_bounds__(THREADS, 2)
void fused_kernel(const float* __restrict__ verts,
                  const float* __restrict__ tnorm,
                  const float* __restrict__ tcent,
                  const int*   __restrict__ sidx,
                  int N, int M, int T, int nBlocks,
                  float* __restrict__ out)
{
    // splatted j-subtile: 8 u64 per j (7 used + 1 pad) = 16 KB
    __shared__ __align__(16) u64 sj[TJ * 8];
    __shared__ double rbuf[THREADS];
    __shared__ int s_last;

    const int tid = threadIdx.x;

    // block -> (triangular tile-pair, j-subtile)
    int unit = blockIdx.x / JSUB;
    const int sub = blockIdx.x % JSUB;
    int ti = 0, row = T;
    while (unit >= row) { unit -= row; ti++; row--; }
    const int tj = ti + unit;
    const float scale = (ti == tj) ? 1.0f : 2.0f;

    const int ibase = ti * ICHUNK;
    const int jt    = tj * ICHUNK + sub * TJ;

    // ---- j prep + splat fill (1 j per thread) ----
    {
        int j = jt + tid;
        float cx, cy, cz, a2, wx, wy, wz;
        make_point(j, N, M, verts, tnorm, tcent, sidx, cx, cy, cz, a2, wx, wy, wz);
        u64* s = &sj[tid * 8];
        s[0] = pack2(-2.f * cx, -2.f * cx);
        s[1] = pack2(-2.f * cy, -2.f * cy);
        s[2] = pack2(-2.f * cz, -2.f * cz);
        s[3] = pack2(1.f + a2, 1.f + a2);
        s[4] = pack2(wx, wx);
        s[5] = pack2(wy, wy);
        s[6] = pack2(wz, wz);
    }

    // ---- i prep: IPT=8 points straight into packed registers ----
    u64 pcx[NCH], pcy[NCH], pcz[NCH], pa2[NCH];
    u64 pwx[NCH], pwy[NCH], pwz[NCH], acc[NCH];
#pragma unroll
    for (int c = 0; c < NCH; c++) {
        float cxA, cyA, czA, a2A, wxA, wyA, wzA;
        float cxB, cyB, czB, a2B, wxB, wyB, wzB;
        int iA = ibase + (2 * c + 0) * THREADS + tid;
        int iB = ibase + (2 * c + 1) * THREADS + tid;
        make_point(iA, N, M, verts, tnorm, tcent, sidx, cxA, cyA, czA, a2A, wxA, wyA, wzA);
        make_point(iB, N, M, verts, tnorm, tcent, sidx, cxB, cyB, czB, a2B, wxB, wyB, wzB);
        pcx[c] = pack2(cxA, cxB);
        pcy[c] = pack2(cyA, cyB);
        pcz[c] = pack2(czA, czB);
        pa2[c] = pack2(a2A, a2B);
        pwx[c] = pack2(wxA, wxB);
        pwy[c] = pack2(wyA, wyB);
        pwz[c] = pack2(wzA, wzB);
        acc[c] = 0ull;
    }

    __syncthreads();

    // ---- main pair loop: reg double-buffered j, stage-batched chains ----
    ulonglong2 n0, n1, n2, n3;
    {
        const ulonglong2* jp = (const ulonglong2*)&sj[0];
        n0 = jp[0]; n1 = jp[1]; n2 = jp[2]; n3 = jp[3];
    }
#pragma unroll 8
    for (int jj = 0; jj < TJ; jj++) {
        const ulonglong2 v0 = n0, v1 = n1, v2 = n2, v3 = n3;
        if (jj + 1 < TJ) {
            const ulonglong2* jp = (const ulonglong2*)&sj[(jj + 1) * 8];
            n0 = jp[0]; n1 = jp[1]; n2 = jp[2]; n3 = jp[3];
        }

        // stage 1: all denominators
        u64 d[NCH];
#pragma unroll
        for (int c = 0; c < NCH; c++) {
            u64 t = add2(pa2[c], v1.y);          // a_i + b_j
            t = fma2(v0.x, pcx[c], t);
            t = fma2(v0.y, pcy[c], t);
            d[c] = fma2(v1.x, pcz[c], t);        // = 1 + |ci-cj|^2
        }
        // stage 2: all reciprocals (8 MUFUs pipelined back-to-back)
        u64 r[NCH];
#pragma unroll
        for (int c = 0; c < NCH; c++) {
            float d0, d1; unpack2(d[c], d0, d1);
            r[c] = pack2(rcpf(d0), rcpf(d1));
        }
        // stage 3: dots + accumulate
#pragma unroll
        for (int c = 0; c < NCH; c++) {
            u64 t = mul2(pwx[c], v2.x);
            t = fma2(pwy[c], v2.y, t);
            t = fma2(pwz[c], v3.x, t);
            acc[c] = fma2(t, r[c], acc[c]);
        }
    }

    // ---- deterministic block reduction (double) ----
    double s = 0.0;
#pragma unroll
    for (int c = 0; c < NCH; c++) {
        float a0, a1;
        unpack2(acc[c], a0, a1);
        s += (double)a0 + (double)a1;
    }
    s *= (double)scale;
    rbuf[tid] = s;
    __syncthreads();
#pragma unroll
    for (int off = THREADS / 2; off > 0; off >>= 1) {
        if (tid < off) rbuf[tid] += rbuf[tid + off];
        __syncthreads();
    }
    if (tid == 0) {
        g_partials[blockIdx.x] = rbuf[0];
        __threadfence();
        unsigned int ticket = atomicAdd(&g_done, 1u);
        s_last = (ticket == (unsigned int)(nBlocks - 1)) ? 1 : 0;
    }
    __syncthreads();

    // ---- last block: fixed-order deterministic final reduction ----
    if (s_last) {
        double fs = 0.0;
        for (int k = tid; k < nBlocks; k += THREADS)   // fixed assignment+order
            fs += g_partials[k];
        rbuf[tid] = fs;
        __syncthreads();
#pragma unroll
        for (int off = THREADS / 2; off > 0; off >>= 1) {
            if (tid < off) rbuf[tid] += rbuf[tid + off];
            __syncthreads();
        }
        if (tid == 0) {
            out[0] = (float)rbuf[0];
            g_done = 0;   // self-restore for next graph replay
        }
    }
}

// ----------------------------------------------------------------------------
extern "C" void kernel_launch(void* const* d_in, const int* in_sizes, int n_in,
                              void* d_out, int out_size)
{
    const float* verts = (const float*)d_in[0];   // src_vertices  (V,3)
    const float* tnorm = (const float*)d_in[1];   // tar_normals   (M,3)
    const float* tcent = (const float*)d_in[2];   // tar_centers   (M,3)
    const int*   sidx  = (const int*)  d_in[3];   // src_indices   (N,3)

    const int N = in_sizes[3] / 3;
    const int M = in_sizes[1] / 3;
    const int total = N + M;
    const int total_pad = ((total + ICHUNK - 1) / ICHUNK) * ICHUNK;
    const int T = total_pad / ICHUNK;             // 8 for 16384 points

    const int nBlocks = (T * (T + 1) / 2) * JSUB;   // 36 * 8 = 288
    fused_kernel<<<nBlocks, THREADS>>>(verts, tnorm, tcent, sidx,
                                       N, M, T, nBlocks, (float*)d_out);
}